// round 14
// baseline (speedup 1.0000x reference)
#include <cuda_runtime.h>

typedef unsigned long long ull;

#define HW 512
#define IMG (512 * 512)

// raw weight layout: 65 ch x 28 floats (27 taps + pad); 65th = zeros (prefetch overrun)
__constant__ __align__(16) float c_w[65 * 28];
__device__ float d_scratch[65 * 28];   // zero-initialized device global

__device__ __forceinline__ ull pk(float lo, float hi) {
    ull r;
    asm("mov.b64 %0, {%1,%2};" : "=l"(r) : "f"(lo), "f"(hi));
    return r;
}
__device__ __forceinline__ ull ffma2(ull a, ull b, ull c) {
    ull d;
    asm("fma.rn.f32x2 %0, %1, %2, %3;" : "=l"(d) : "l"(a), "l"(b), "l"(c));
    return d;
}
__device__ __forceinline__ ull fadd2(ull a, ull b) {
    ull d;
    asm("add.rn.f32x2 %0, %1, %2;" : "=l"(d) : "l"(a), "l"(b));
    return d;
}
// (a.hi, b.lo)
__device__ __forceinline__ ull cross(ull a, ull b) {
    ull r;
    asm("{\n\t"
        ".reg .b32 al, ah, bl, bh;\n\t"
        "mov.b64 {al, ah}, %1;\n\t"
        "mov.b64 {bl, bh}, %2;\n\t"
        "mov.b64 %0, {ah, bl};\n\t"
        "}" : "=l"(r) : "l"(a), "l"(b));
    return r;
}
// volatile constant-bank vector load: NVVM cannot rematerialize/sink it
__device__ __forceinline__ float4 ldc4(const float4* p) {
    float4 v;
    asm volatile(
        "{\n\t.reg .u64 a;\n\t"
        "cvta.to.const.u64 a, %4;\n\t"
        "ld.const.v4.f32 {%0, %1, %2, %3}, [a];\n\t}"
        : "=f"(v.x), "=f"(v.y), "=f"(v.z), "=f"(v.w) : "l"(p));
    return v;
}

__global__ void prep_weights(const float* __restrict__ wm) {
    int i = blockIdx.x * blockDim.x + threadIdx.x;   // over 64*28 slots
    if (i < 64 * 28) {
        int c = i / 28, s = i - c * 28;
        d_scratch[i] = (s < 27) ? wm[c * 27 + s] : 0.f;
    }
}

// one tap-row: build 3 (w,w) pairs from scalars (ALU), then 13 FFMA2
#define TAPROW(R) { \
    ull p0 = pk(wv[3*(R)],   wv[3*(R)]); \
    ull p2 = pk(wv[3*(R)+2], wv[3*(R)+2]); \
    F0 = ffma2(p0, W[R][0], F0); F1 = ffma2(p0, W[R][1], F1); \
    F2 = ffma2(p0, W[R][2], F2); F3 = ffma2(p0, W[R][3], F3); \
    F0 = ffma2(p2, W[R][1], F0); F1 = ffma2(p2, W[R][2], F1); \
    F2 = ffma2(p2, W[R][3], F2); F3 = ffma2(p2, W[R][4], F3); \
    ull p1 = pk(wv[3*(R)+1], wv[3*(R)+1]); \
    E0 = ffma2(p1, W[R][0], E0); E1 = ffma2(p1, W[R][1], E1); \
    E2 = ffma2(p1, W[R][2], E2); E3 = ffma2(p1, W[R][3], E3); \
    E4 = ffma2(p1, W[R][4], E4); }

#define UNPACK(Q0,Q1,Q2,Q3,Q4,Q5,Q6) \
    wv[0]=Q0.x;  wv[1]=Q0.y;  wv[2]=Q0.z;  wv[3]=Q0.w; \
    wv[4]=Q1.x;  wv[5]=Q1.y;  wv[6]=Q1.z;  wv[7]=Q1.w; \
    wv[8]=Q2.x;  wv[9]=Q2.y;  wv[10]=Q2.z; wv[11]=Q2.w; \
    wv[12]=Q3.x; wv[13]=Q3.y; wv[14]=Q3.z; wv[15]=Q3.w; \
    wv[16]=Q4.x; wv[17]=Q4.y; wv[18]=Q4.z; wv[19]=Q4.w; \
    wv[20]=Q5.x; wv[21]=Q5.y; wv[22]=Q5.z; wv[23]=Q5.w; \
    wv[24]=Q6.x; wv[25]=Q6.y; wv[26]=Q6.z; wv[27]=Q6.w;

#define CHLOOP(ROWADJ) { \
    const float4* cw4 = (const float4*)c_w; \
    float4 cur0 = ldc4(cw4+0), cur1 = ldc4(cw4+1), cur2 = ldc4(cw4+2), \
           cur3 = ldc4(cw4+3), cur4 = ldc4(cw4+4), cur5 = ldc4(cw4+5), \
           cur6 = ldc4(cw4+6); \
    _Pragma("unroll 2") \
    for (int c = 0; c < 64; c++) { \
        const float4* nb = cw4 + (c + 1) * 7; \
        float4 n0 = ldc4(nb+0), n1 = ldc4(nb+1), n2 = ldc4(nb+2), \
               n3 = ldc4(nb+3), n4 = ldc4(nb+4), n5 = ldc4(nb+5), \
               n6 = ldc4(nb+6); \
        float wv[28]; \
        UNPACK(cur0, cur1, cur2, cur3, cur4, cur5, cur6) \
        ull bp = sBase[c]; \
        ull F0 = aptr[c], F1 = bp, F2 = bp, F3 = dptr[c]; \
        ull E0 = 0ULL, E1 = 0ULL, E2 = 0ULL, E3 = 0ULL, E4 = 0ULL; \
        if (ROWADJ) { \
            float adj = rowc[c]; \
            float aL = adj + (isL ? cornL[c] : 0.f); \
            float aR = adj + (isR ? cornR[c] : 0.f); \
            ull adjp = pk(adj, adj); \
            F0 = fadd2(F0, pk(aL, adj)); F1 = fadd2(F1, adjp); \
            F2 = fadd2(F2, adjp);        F3 = fadd2(F3, pk(adj, aR)); \
        } \
        TAPROW(0) TAPROW(1) TAPROW(2) TAPROW(3) TAPROW(4) \
        TAPROW(5) TAPROW(6) TAPROW(7) TAPROW(8) \
        ulonglong2 r01, r23; \
        r01.x = fadd2(F0, cross(E0, E1)); \
        r01.y = fadd2(F1, cross(E1, E2)); \
        r23.x = fadd2(F2, cross(E2, E3)); \
        r23.y = fadd2(F3, cross(E3, E4)); \
        float* op = outp + (size_t)c * IMG; \
        *reinterpret_cast<ulonglong2*>(op)     = r01; \
        *reinterpret_cast<ulonglong2*>(op + 4) = r23; \
        cur0 = n0; cur1 = n1; cur2 = n2; cur3 = n3; \
        cur4 = n4; cur5 = n5; cur6 = n6; \
    } }

__global__ void __launch_bounds__(128, 3) conv_main(
    const float* __restrict__ x,   // [8,3,512,512]
    const float* __restrict__ ei,  // [8,192]
    const float* __restrict__ bm,  // [64]
    const float* __restrict__ we,  // [64,3,3,3]
    const float* __restrict__ be,  // [64]
    float* __restrict__ out)       // [8,64,512,512]
{
    __shared__ __align__(16) float xs[3][6][260];   // rows h0-1..h0+4, cols w0-1..w0+256
    __shared__ ull sBase[64], sBaseL[64], sBaseR[64];
    __shared__ float sCT[64], sCB[64], sTL[64], sTR[64], sBL[64], sBR[64];

    const int tid = threadIdx.x, lane = tid & 31, wid = tid >> 5;
    const int cx = blockIdx.x, ty = blockIdx.y, b = blockIdx.z;
    const int w0 = cx * 256, h0 = ty * 4;

    // ---- stage input patch (zero padded) ----
    for (int i = tid; i < 3 * 6 * 258; i += 128) {
        int ci = i / 1548;
        int rem = i - ci * 1548;
        int rr = rem / 258, j = rem - rr * 258;
        int gh = h0 - 1 + rr, gw = w0 - 1 + j;
        float v = 0.f;
        if ((unsigned)gh < 512u && (unsigned)gw < 512u)
            v = x[((b * 3 + ci) * HW + gh) * HW + gw];
        xs[ci][rr][j] = v;
    }

    // ---- per-channel extra-term scalars ----
    if (tid < 64) {
        int c = tid;
        float S = 0, rT = 0, rB = 0, kL = 0, kR = 0;
        float tTL = 0, tTR = 0, tBL = 0, tBR = 0;
        #pragma unroll
        for (int e = 0; e < 3; e++) {
            float v = __ldg(ei + b * 192 + c * 3 + e);
            const float* wq = we + (c * 3 + e) * 9;
            #pragma unroll
            for (int ky = 0; ky < 3; ky++) {
                #pragma unroll
                for (int kx = 0; kx < 3; kx++) {
                    float t = v * __ldg(wq + ky * 3 + kx);
                    S += t;
                    if (ky == 0) rT += t;
                    if (ky == 2) rB += t;
                    if (kx == 0) kL += t;
                    if (kx == 2) kR += t;
                    if (ky == 0 && kx == 0) tTL += t;
                    if (ky == 0 && kx == 2) tTR += t;
                    if (ky == 2 && kx == 0) tBL += t;
                    if (ky == 2 && kx == 2) tBR += t;
                }
            }
        }
        float base = __ldg(bm + c) + __ldg(be + c) + S;
        sBase[c]  = pk(base, base);
        sBaseL[c] = pk(base - kL, base);
        sBaseR[c] = pk(base, base - kR);
        sCT[c] = -rT; sCB[c] = -rB;
        sTL[c] = tTL; sTR[c] = tTR; sBL[c] = tBL; sBR[c] = tBR;
    }
    __syncthreads();

    // ---- build 9x5 register window of aligned pairs q0..q4 per (ci,dy) row ----
    ull W[9][5];
    #pragma unroll
    for (int ci = 0; ci < 3; ci++) {
        #pragma unroll
        for (int dy = 0; dy < 3; dy++) {
            const float* p = &xs[ci][wid + dy][lane * 8];
            ulonglong2 q01 = *reinterpret_cast<const ulonglong2*>(p);
            ulonglong2 q23 = *reinterpret_cast<const ulonglong2*>(p + 4);
            ull q4 = *reinterpret_cast<const ull*>(p + 8);
            int r = ci * 3 + dy;
            W[r][0] = q01.x; W[r][1] = q01.y; W[r][2] = q23.x;
            W[r][3] = q23.y; W[r][4] = q4;
        }
    }

    const int h = h0 + wid;
    const bool isL = (cx == 0) && (lane == 0);
    const bool isR = (cx == 1) && (lane == 31);
    const bool top = (h == 0), bot = (h == HW - 1);

    const ull* aptr = isL ? sBaseL : sBase;
    const ull* dptr = isR ? sBaseR : sBase;

    float* outp = out + (((size_t)b * 64) * HW + h) * HW + w0 + lane * 8;

    if (!(top | bot)) {
        const float* rowc = sCT;
        const float* cornL = sTL;
        const float* cornR = sTR;
        (void)rowc; (void)cornL; (void)cornR;
        CHLOOP(false)
    } else {
        const float* rowc  = top ? sCT : sCB;
        const float* cornL = top ? sTL : sBL;
        const float* cornR = top ? sTR : sBR;
        CHLOOP(true)
    }
}

extern "C" void kernel_launch(void* const* d_in, const int* in_sizes, int n_in,
                              void* d_out, int out_size)
{
    const float* x  = (const float*)d_in[0];
    const float* ei = (const float*)d_in[1];
    const float* wm = (const float*)d_in[2];
    const float* bm = (const float*)d_in[3];
    const float* we = (const float*)d_in[4];
    const float* be = (const float*)d_in[5];
    float* out = (float*)d_out;

    prep_weights<<<(64 * 28 + 255) / 256, 256>>>(wm);

    void* scratch_ptr = nullptr;
    cudaGetSymbolAddress(&scratch_ptr, d_scratch);
    cudaMemcpyToSymbolAsync(c_w, scratch_ptr, sizeof(float) * 65 * 28, 0,
                            cudaMemcpyDeviceToDevice, 0);

    dim3 grid(2, 128, 8);   // 2 col-blocks x 128 row-blocks x 8 batches = 2048 CTAs
    conv_main<<<grid, 128>>>(x, ei, bm, we, be, out);
}

// round 15
// speedup vs baseline: 1.0933x; 1.0933x over previous
#include <cuda_runtime.h>

typedef unsigned long long ull;

#define HW 512
#define IMG (512 * 512)

// raw weight layout: 64 ch x 28 floats (27 taps + pad) = 112B/ch -> 7 LDC.128
__constant__ __align__(16) float c_w[64 * 28];
__device__ float d_scratch[64 * 28];

__device__ __forceinline__ ull pk(float lo, float hi) {
    ull r;
    asm("mov.b64 %0, {%1,%2};" : "=l"(r) : "f"(lo), "f"(hi));
    return r;
}
__device__ __forceinline__ ull ffma2(ull a, ull b, ull c) {
    ull d;
    asm("fma.rn.f32x2 %0, %1, %2, %3;" : "=l"(d) : "l"(a), "l"(b), "l"(c));
    return d;
}
__device__ __forceinline__ ull fadd2(ull a, ull b) {
    ull d;
    asm("add.rn.f32x2 %0, %1, %2;" : "=l"(d) : "l"(a), "l"(b));
    return d;
}
// (a.hi, b.lo)
__device__ __forceinline__ ull cross(ull a, ull b) {
    ull r;
    asm("{\n\t"
        ".reg .b32 al, ah, bl, bh;\n\t"
        "mov.b64 {al, ah}, %1;\n\t"
        "mov.b64 {bl, bh}, %2;\n\t"
        "mov.b64 %0, {ah, bl};\n\t"
        "}" : "=l"(r) : "l"(a), "l"(b));
    return r;
}

__global__ void prep_weights(const float* __restrict__ wm) {
    int i = blockIdx.x * blockDim.x + threadIdx.x;
    if (i < 64 * 28) {
        int c = i / 28, s = i - c * 28;
        d_scratch[i] = (s < 27) ? wm[c * 27 + s] : 0.f;
    }
}

// one (ci,ky) tap: build 3 pairs once, apply to BOTH output rows (26 FFMA2)
#define TAPROW2(CI, KY) { \
    const int t = 3 * ((CI) * 3 + (KY)); \
    const int RA = (CI) * 4 + (KY), RB = RA + 1; \
    ull p0 = pk(wv[t], wv[t]); \
    ull p2 = pk(wv[t + 2], wv[t + 2]); \
    FA0 = ffma2(p0, W[RA][0], FA0); FA1 = ffma2(p0, W[RA][1], FA1); \
    FA2 = ffma2(p0, W[RA][2], FA2); FA3 = ffma2(p0, W[RA][3], FA3); \
    FB0 = ffma2(p0, W[RB][0], FB0); FB1 = ffma2(p0, W[RB][1], FB1); \
    FB2 = ffma2(p0, W[RB][2], FB2); FB3 = ffma2(p0, W[RB][3], FB3); \
    FA0 = ffma2(p2, W[RA][1], FA0); FA1 = ffma2(p2, W[RA][2], FA1); \
    FA2 = ffma2(p2, W[RA][3], FA2); FA3 = ffma2(p2, W[RA][4], FA3); \
    FB0 = ffma2(p2, W[RB][1], FB0); FB1 = ffma2(p2, W[RB][2], FB1); \
    FB2 = ffma2(p2, W[RB][3], FB2); FB3 = ffma2(p2, W[RB][4], FB3); \
    ull p1 = pk(wv[t + 1], wv[t + 1]); \
    EA0 = ffma2(p1, W[RA][0], EA0); EA1 = ffma2(p1, W[RA][1], EA1); \
    EA2 = ffma2(p1, W[RA][2], EA2); EA3 = ffma2(p1, W[RA][3], EA3); \
    EA4 = ffma2(p1, W[RA][4], EA4); \
    EB0 = ffma2(p1, W[RB][0], EB0); EB1 = ffma2(p1, W[RB][1], EB1); \
    EB2 = ffma2(p1, W[RB][2], EB2); EB3 = ffma2(p1, W[RB][3], EB3); \
    EB4 = ffma2(p1, W[RB][4], EB4); }

#define UNPACK(Q0,Q1,Q2,Q3,Q4,Q5,Q6) \
    wv[0]=Q0.x;  wv[1]=Q0.y;  wv[2]=Q0.z;  wv[3]=Q0.w; \
    wv[4]=Q1.x;  wv[5]=Q1.y;  wv[6]=Q1.z;  wv[7]=Q1.w; \
    wv[8]=Q2.x;  wv[9]=Q2.y;  wv[10]=Q2.z; wv[11]=Q2.w; \
    wv[12]=Q3.x; wv[13]=Q3.y; wv[14]=Q3.z; wv[15]=Q3.w; \
    wv[16]=Q4.x; wv[17]=Q4.y; wv[18]=Q4.z; wv[19]=Q4.w; \
    wv[20]=Q5.x; wv[21]=Q5.y; wv[22]=Q5.z; wv[23]=Q5.w; \
    wv[24]=Q6.x; wv[25]=Q6.y; wv[26]=Q6.z; wv[27]=Q6.w;

#define CHLOOP(ROWADJ) \
    _Pragma("unroll 1") \
    for (int c = 0; c < 64; c++) { \
        const float4* cw4 = (const float4*)(c_w + c * 28); \
        float4 q0 = cw4[0], q1 = cw4[1], q2 = cw4[2], q3 = cw4[3]; \
        float4 q4 = cw4[4], q5 = cw4[5], q6 = cw4[6]; \
        float wv[28]; \
        UNPACK(q0, q1, q2, q3, q4, q5, q6) \
        ull bp = sBase[c], ap = aptr[c], dp = dptr[c]; \
        ull FA0 = ap, FA1 = bp, FA2 = bp, FA3 = dp; \
        ull FB0 = ap, FB1 = bp, FB2 = bp, FB3 = dp; \
        ull EA0 = 0ULL, EA1 = 0ULL, EA2 = 0ULL, EA3 = 0ULL, EA4 = 0ULL; \
        ull EB0 = 0ULL, EB1 = 0ULL, EB2 = 0ULL, EB3 = 0ULL, EB4 = 0ULL; \
        if (ROWADJ) { \
            float adjA = mtA * sCT[c]; \
            float adjB = mbB * sCB[c]; \
            float aLA = adjA + (isL ? mtA * sTL[c] : 0.f); \
            float aRA = adjA + (isR ? mtA * sTR[c] : 0.f); \
            float aLB = adjB + (isL ? mbB * sBL[c] : 0.f); \
            float aRB = adjB + (isR ? mbB * sBR[c] : 0.f); \
            ull adjpA = pk(adjA, adjA), adjpB = pk(adjB, adjB); \
            FA0 = fadd2(FA0, pk(aLA, adjA)); FA1 = fadd2(FA1, adjpA); \
            FA2 = fadd2(FA2, adjpA);         FA3 = fadd2(FA3, pk(adjA, aRA)); \
            FB0 = fadd2(FB0, pk(aLB, adjB)); FB1 = fadd2(FB1, adjpB); \
            FB2 = fadd2(FB2, adjpB);         FB3 = fadd2(FB3, pk(adjB, aRB)); \
        } \
        TAPROW2(0, 0) TAPROW2(0, 1) TAPROW2(0, 2) \
        TAPROW2(1, 0) TAPROW2(1, 1) TAPROW2(1, 2) \
        TAPROW2(2, 0) TAPROW2(2, 1) TAPROW2(2, 2) \
        ulonglong2 rA01, rA23, rB01, rB23; \
        rA01.x = fadd2(FA0, cross(EA0, EA1)); \
        rA01.y = fadd2(FA1, cross(EA1, EA2)); \
        rA23.x = fadd2(FA2, cross(EA2, EA3)); \
        rA23.y = fadd2(FA3, cross(EA3, EA4)); \
        rB01.x = fadd2(FB0, cross(EB0, EB1)); \
        rB01.y = fadd2(FB1, cross(EB1, EB2)); \
        rB23.x = fadd2(FB2, cross(EB2, EB3)); \
        rB23.y = fadd2(FB3, cross(EB3, EB4)); \
        float* op = outp + (size_t)c * IMG; \
        *reinterpret_cast<ulonglong2*>(op)       = rA01; \
        *reinterpret_cast<ulonglong2*>(op + 4)   = rA23; \
        *reinterpret_cast<ulonglong2*>(op + 512) = rB01; \
        *reinterpret_cast<ulonglong2*>(op + 516) = rB23; \
    }

__global__ void __launch_bounds__(128, 2) conv_main(
    const float* __restrict__ x,   // [8,3,512,512]
    const float* __restrict__ ei,  // [8,192]
    const float* __restrict__ bm,  // [64]
    const float* __restrict__ we,  // [64,3,3,3]
    const float* __restrict__ be,  // [64]
    float* __restrict__ out)       // [8,64,512,512]
{
    __shared__ __align__(16) float xs[3][10][260];  // rows h0-1..h0+8, cols w0-1..w0+256
    __shared__ ull sBase[64], sBaseL[64], sBaseR[64];
    __shared__ float sCT[64], sCB[64], sTL[64], sTR[64], sBL[64], sBR[64];

    const int tid = threadIdx.x, lane = tid & 31, wid = tid >> 5;
    const int cx = blockIdx.x, ty = blockIdx.y, b = blockIdx.z;
    const int w0 = cx * 256, h0 = ty * 8;

    // ---- stage input patch: 10 rows x 258 cols x 3 ci (zero padded) ----
    for (int i = tid; i < 3 * 10 * 258; i += 128) {
        int ci = i / 2580;
        int rem = i - ci * 2580;
        int rr = rem / 258, j = rem - rr * 258;
        int gh = h0 - 1 + rr, gw = w0 - 1 + j;
        float v = 0.f;
        if ((unsigned)gh < 512u && (unsigned)gw < 512u)
            v = x[((b * 3 + ci) * HW + gh) * HW + gw];
        xs[ci][rr][j] = v;
    }

    // ---- per-channel extra-term scalars ----
    if (tid < 64) {
        int c = tid;
        float S = 0, rT = 0, rB = 0, kL = 0, kR = 0;
        float tTL = 0, tTR = 0, tBL = 0, tBR = 0;
        #pragma unroll
        for (int e = 0; e < 3; e++) {
            float v = __ldg(ei + b * 192 + c * 3 + e);
            const float* wq = we + (c * 3 + e) * 9;
            #pragma unroll
            for (int ky = 0; ky < 3; ky++) {
                #pragma unroll
                for (int kx = 0; kx < 3; kx++) {
                    float t = v * __ldg(wq + ky * 3 + kx);
                    S += t;
                    if (ky == 0) rT += t;
                    if (ky == 2) rB += t;
                    if (kx == 0) kL += t;
                    if (kx == 2) kR += t;
                    if (ky == 0 && kx == 0) tTL += t;
                    if (ky == 0 && kx == 2) tTR += t;
                    if (ky == 2 && kx == 0) tBL += t;
                    if (ky == 2 && kx == 2) tBR += t;
                }
            }
        }
        float base = __ldg(bm + c) + __ldg(be + c) + S;
        sBase[c]  = pk(base, base);
        sBaseL[c] = pk(base - kL, base);
        sBaseR[c] = pk(base, base - kR);
        sCT[c] = -rT; sCB[c] = -rB;
        sTL[c] = tTL; sTR[c] = tTR; sBL[c] = tBL; sBR[c] = tBR;
    }
    __syncthreads();

    // ---- 12-row register window: input rows 2*wid .. 2*wid+3 per ci ----
    ull W[12][5];
    #pragma unroll
    for (int ci = 0; ci < 3; ci++) {
        #pragma unroll
        for (int j = 0; j < 4; j++) {
            const float* p = &xs[ci][2 * wid + j][lane * 8];
            ulonglong2 q01 = *reinterpret_cast<const ulonglong2*>(p);
            ulonglong2 q23 = *reinterpret_cast<const ulonglong2*>(p + 4);
            ull q4 = *reinterpret_cast<const ull*>(p + 8);
            int r = ci * 4 + j;
            W[r][0] = q01.x; W[r][1] = q01.y; W[r][2] = q23.x;
            W[r][3] = q23.y; W[r][4] = q4;
        }
    }

    const int hA = h0 + 2 * wid;              // row A; row B = hA+1
    const bool isL = (cx == 0) && (lane == 0);
    const bool isR = (cx == 1) && (lane == 31);
    const bool topA = (hA == 0), botB = (hA + 1 == HW - 1);
    const float mtA = topA ? 1.f : 0.f, mbB = botB ? 1.f : 0.f;

    const ull* aptr = isL ? sBaseL : sBase;
    const ull* dptr = isR ? sBaseR : sBase;

    float* outp = out + (((size_t)b * 64) * HW + hA) * HW + w0 + lane * 8;

    if (!(topA | botB)) {
        CHLOOP(false)
    } else {
        CHLOOP(true)
    }
}

extern "C" void kernel_launch(void* const* d_in, const int* in_sizes, int n_in,
                              void* d_out, int out_size)
{
    const float* x  = (const float*)d_in[0];
    const float* ei = (const float*)d_in[1];
    const float* wm = (const float*)d_in[2];
    const float* bm = (const float*)d_in[3];
    const float* we = (const float*)d_in[4];
    const float* be = (const float*)d_in[5];
    float* out = (float*)d_out;

    prep_weights<<<(64 * 28 + 255) / 256, 256>>>(wm);

    void* scratch_ptr = nullptr;
    cudaGetSymbolAddress(&scratch_ptr, d_scratch);
    cudaMemcpyToSymbolAsync(c_w, scratch_ptr, sizeof(float) * 64 * 28, 0,
                            cudaMemcpyDeviceToDevice, 0);

    dim3 grid(2, 64, 8);   // 2 col-blocks x 64 row-blocks(8 rows) x 8 batches = 1024 CTAs
    conv_main<<<grid, 128>>>(x, ei, bm, we, be, out);
}